// round 1
// baseline (speedup 1.0000x reference)
#include <cuda_runtime.h>
#include <cstdint>

// ---------------------------------------------------------------------------
// Problem: out[b,o,v,l] = sum_c W[o,c] * (M x)[b,c,v,l] + bias[o]
// where M = a*I + a(1-a)A + a(1-a)^2 A^2 + (1-a)^3 A^3,  a = 0.05,
// A = row-normalized (adj + I).
// Shapes: x (256,32,207,12) f32, adj (207,207), W (32,32), b (32).
// ---------------------------------------------------------------------------

#define NNODES 207
#define BATCH  256
#define CH     32
#define LT     12              // timesteps (contiguous)
#define ROWF   (NNODES * LT)   // 2484 floats per (b,c) slab

// scratch (allocation-free rule: __device__ globals)
static __device__ float g_a [NNODES * NNODES];
static __device__ float g_a2[NNODES * NNODES];
static __device__ float g_Mt[NNODES * NNODES];              // Mt[w*207+v] = M[v][w]
static __device__ float g_u [BATCH * CH * NNODES * LT];     // channel-mixed intermediate (81.4 MB)

typedef unsigned long long ull;

// packed f32x2 FMA (PTX-only path; 2x FFMA throughput on sm_103a)
#define FMA_F32X2(d, a, b, c) \
    asm("fma.rn.f32x2 %0, %1, %2, %3;" : "=l"(d) : "l"(a), "l"(b), "l"(c))

__device__ __forceinline__ ull pack2(float x) {
    ull r;
    unsigned int xi = __float_as_uint(x);
    asm("mov.b64 %0, {%1, %1};" : "=l"(r) : "r"(xi));
    return r;
}

// ---------------------------------------------------------------------------
// K1: row-normalize (adj + I)
// ---------------------------------------------------------------------------
__global__ void k_norm_adj(const float* __restrict__ adj) {
    int v = blockIdx.x;
    int t = threadIdx.x;
    __shared__ float red[256];
    float s = 0.f;
    for (int w = t; w < NNODES; w += 256) s += adj[v * NNODES + w];
    red[t] = s;
    __syncthreads();
    for (int k = 128; k > 0; k >>= 1) {
        if (t < k) red[t] += red[t + k];
        __syncthreads();
    }
    float inv = 1.f / (red[0] + 1.f);   // +1 for self loop on the diagonal
    for (int w = t; w < NNODES; w += 256) {
        float e = adj[v * NNODES + w] + (w == v ? 1.f : 0.f);
        g_a[v * NNODES + w] = e * inv;
    }
}

// ---------------------------------------------------------------------------
// K2: a2 = a @ a    (one block per output row)
// ---------------------------------------------------------------------------
__global__ void k_a2() {
    int v = blockIdx.x;
    int t = threadIdx.x;
    __shared__ float av[NNODES];
    for (int w = t; w < NNODES; w += 224) av[w] = g_a[v * NNODES + w];
    __syncthreads();
    if (t < NNODES) {
        float acc = 0.f;
        #pragma unroll 4
        for (int w = 0; w < NNODES; ++w) acc = fmaf(av[w], g_a[w * NNODES + t], acc);
        g_a2[v * NNODES + t] = acc;
    }
}

// ---------------------------------------------------------------------------
// K3: a3 = a2 @ a, combine into Mt (transposed for coalesced reads later)
// ---------------------------------------------------------------------------
__global__ void k_m() {
    int v = blockIdx.x;
    int t = threadIdx.x;
    __shared__ float av[NNODES], a2v[NNODES];
    for (int w = t; w < NNODES; w += 224) {
        av[w]  = g_a [v * NNODES + w];
        a2v[w] = g_a2[v * NNODES + w];
    }
    __syncthreads();
    if (t < NNODES) {
        float a3 = 0.f;
        #pragma unroll 4
        for (int w = 0; w < NNODES; ++w) a3 = fmaf(a2v[w], g_a[w * NNODES + t], a3);
        // alpha = 0.05:  a(1-a)=0.0475, a(1-a)^2=0.045125, (1-a)^3=0.857375
        float m = 0.0475f * av[t] + 0.045125f * a2v[t] + 0.857375f * a3;
        if (t == v) m += 0.05f;
        g_Mt[t * NNODES + v] = m;   // Mt[w][v] = M[v][w]
    }
}

// ---------------------------------------------------------------------------
// K4: channel mix  u[b,o,w,l] = sum_c W[o,c] x[b,c,w,l]
// grid: (ceil(207/16), 256), block 256
// ---------------------------------------------------------------------------
#define WT 16
__global__ void k_chanmix(const float* __restrict__ x, const float* __restrict__ W) {
    int b  = blockIdx.y;
    int w0 = blockIdx.x * WT;
    int nw = NNODES - w0; if (nw > WT) nw = WT;
    int t  = threadIdx.x;

    __shared__ __align__(16) float4 xs[CH * WT * 3];   // [c][wi][l4]  24.6 KB
    __shared__ float Ws[CH * CH];                      // 4 KB

    for (int i = t; i < CH * CH; i += 256) Ws[i] = W[i];
    int nload = CH * nw * 3;
    for (int i = t; i < nload; i += 256) {
        int c  = i / (nw * 3);
        int r  = i - c * nw * 3;
        int wi = r / 3;
        int l4 = r - wi * 3;
        const float* src = x + ((size_t)(b * CH + c) * NNODES + (w0 + wi)) * LT + l4 * 4;
        xs[(c * WT + wi) * 3 + l4] = *(const float4*)src;
    }
    __syncthreads();

    int npairs = CH * nw;
    for (int p = t; p < npairs; p += 256) {
        int o  = p / nw;
        int wi = p - o * nw;
        float4 a0 = {0,0,0,0}, a1 = {0,0,0,0}, a2 = {0,0,0,0};
        #pragma unroll
        for (int c = 0; c < CH; ++c) {
            float wv = Ws[o * CH + c];
            float4 v0 = xs[(c * WT + wi) * 3 + 0];
            float4 v1 = xs[(c * WT + wi) * 3 + 1];
            float4 v2 = xs[(c * WT + wi) * 3 + 2];
            a0.x = fmaf(wv, v0.x, a0.x); a0.y = fmaf(wv, v0.y, a0.y);
            a0.z = fmaf(wv, v0.z, a0.z); a0.w = fmaf(wv, v0.w, a0.w);
            a1.x = fmaf(wv, v1.x, a1.x); a1.y = fmaf(wv, v1.y, a1.y);
            a1.z = fmaf(wv, v1.z, a1.z); a1.w = fmaf(wv, v1.w, a1.w);
            a2.x = fmaf(wv, v2.x, a2.x); a2.y = fmaf(wv, v2.y, a2.y);
            a2.z = fmaf(wv, v2.z, a2.z); a2.w = fmaf(wv, v2.w, a2.w);
        }
        float* up = g_u + ((size_t)(b * CH + o) * NNODES + (w0 + wi)) * LT;
        *(float4*)(up + 0) = a0;
        *(float4*)(up + 4) = a1;
        *(float4*)(up + 8) = a2;
    }
}

// ---------------------------------------------------------------------------
// K5: node mix  out[b,o,v,:] = sum_w M[v,w] u[b,o,w,:] + bias[o]
// grid: (32 o, 256 b), block 224 (thread = v)
// Heavy kernel: 4.2G FMA done as f32x2 (6 packed accumulators over l=12)
// ---------------------------------------------------------------------------
__global__ void __launch_bounds__(224) k_nodemix(const float* __restrict__ bias,
                                                float* __restrict__ out) {
    int o = blockIdx.x;
    int b = blockIdx.y;
    int t = threadIdx.x;

    __shared__ __align__(16) float us[NNODES * LT];   // 9.94 KB

    const float* up = g_u + (size_t)(b * CH + o) * ROWF;
    for (int i = t; i < (NNODES * LT) / 4; i += 224)
        ((float4*)us)[i] = ((const float4*)up)[i];
    __syncthreads();

    if (t < NNODES) {
        ull acc0 = 0, acc1 = 0, acc2 = 0, acc3 = 0, acc4 = 0, acc5 = 0;
        const float* mt = g_Mt + t;   // Mt[w*207 + v], coalesced across threads
        #pragma unroll 3
        for (int w = 0; w < NNODES; ++w) {
            ull mm = pack2(mt[w * NNODES]);
            const ulonglong2* uw = (const ulonglong2*)(us + w * LT);
            ulonglong2 p0 = uw[0], p1 = uw[1], p2 = uw[2];
            FMA_F32X2(acc0, mm, p0.x, acc0);
            FMA_F32X2(acc1, mm, p0.y, acc1);
            FMA_F32X2(acc2, mm, p1.x, acc2);
            FMA_F32X2(acc3, mm, p1.y, acc3);
            FMA_F32X2(acc4, mm, p2.x, acc4);
            FMA_F32X2(acc5, mm, p2.y, acc5);
        }
        float bv = bias[o];
        float r[12];
        ull a[6] = {acc0, acc1, acc2, acc3, acc4, acc5};
        #pragma unroll
        for (int i = 0; i < 6; ++i) {
            r[2*i]   = __uint_as_float((unsigned)(a[i]       )) + bv;
            r[2*i+1] = __uint_as_float((unsigned)(a[i] >> 32 )) + bv;
        }
        float* op = out + ((size_t)(b * CH + o) * NNODES + t) * LT;
        *(float4*)(op + 0) = *(float4*)(r + 0);
        *(float4*)(op + 4) = *(float4*)(r + 4);
        *(float4*)(op + 8) = *(float4*)(r + 8);
    }
}

// ---------------------------------------------------------------------------
// launch
// ---------------------------------------------------------------------------
extern "C" void kernel_launch(void* const* d_in, const int* in_sizes, int n_in,
                              void* d_out, int out_size) {
    const float* x   = (const float*)d_in[0];
    const float* adj = (const float*)d_in[1];
    const float* W   = (const float*)d_in[2];
    const float* bia = (const float*)d_in[3];
    float* out = (float*)d_out;

    k_norm_adj<<<NNODES, 256>>>(adj);
    k_a2      <<<NNODES, 224>>>();
    k_m       <<<NNODES, 224>>>();
    k_chanmix <<<dim3((NNODES + WT - 1) / WT, BATCH), 256>>>(x, W);
    k_nodemix <<<dim3(CH, BATCH), 224>>>(bia, out);
}